// round 4
// baseline (speedup 1.0000x reference)
#include <cuda_runtime.h>
#include <cstdint>
#include <math.h>

#define BB 8192

// TF32 quantization (matches cuBLAS/cuDNN TF32 operand rounding)
__device__ __forceinline__ float tf32r(float x) {
    uint32_t u;
    asm("cvt.rna.tf32.f32 %0, %1;" : "=r"(u) : "f"(x));
    return __uint_as_float(u);
}

// ---------------- scratch (static device globals; allocation-free) ----------
__device__ float g_A[96 * 96];                 // normalized adjacency (A+I, sym-norm)
__device__ float g_buf1[(size_t)BB * 6144];    // ping
__device__ float g_buf2[(size_t)BB * 3072];    // pong

// ---------------- build dense normalized adjacency (ne edges + 96 loops) ----
__global__ void k_build_adj(const int* __restrict__ ei, int ne) {
    __shared__ float deg[96];
    __shared__ float dinv[96];
    int t = threadIdx.x;
    if (t < 96) deg[t] = 0.f;
    for (int i = t; i < 9216; i += 256) g_A[i] = 0.f;
    __syncthreads();
    for (int e = t; e < ne; e += 256) atomicAdd(&deg[ei[e]], 1.0f);   // targets
    if (t < 96) atomicAdd(&deg[t], 1.0f);                             // self loops
    __syncthreads();
    if (t < 96) dinv[t] = 1.0f / sqrtf(fmaxf(deg[t], 1e-12f));
    __syncthreads();
    for (int e = t; e < ne; e += 256) {
        int r = ei[e], c = ei[ne + e];
        atomicAdd(&g_A[r * 96 + c], dinv[r] * dinv[c]);
    }
    if (t < 96) atomicAdd(&g_A[t * 96 + t], dinv[t] * dinv[t]);
}

// ---------------- GCN1: out = relu((A @ Xq) @ W1q + b1), X = src^T ----------
__global__ void k_gcn1(const float* __restrict__ src, const float* __restrict__ W1,
                       const float* __restrict__ b1) {
    extern __shared__ float sm[];
    float* sA = sm;               // 96*97 (padded), exact
    float* sX = sA + 96 * 97;     // [m][c] 96*16, tf32
    float* sY = sX + 1536;        // [n][c] 96*16, exact intermediate
    float* sW = sY + 1536;        // 16*64, tf32
    float* sB = sW + 1024;        // 64
    int t = threadIdx.x, b = blockIdx.x;

    for (int i = t; i < 9216; i += 256) sA[(i / 96) * 97 + (i % 96)] = g_A[i];
    const float* xb = src + (size_t)b * 1536;
    for (int i = t; i < 1536; i += 256) { int c = i / 96, m = i % 96; sX[m * 16 + c] = tf32r(xb[i]); }
    for (int i = t; i < 1024; i += 256) sW[i] = tf32r(W1[i]);
    if (t < 64) sB[t] = b1[t];
    __syncthreads();

    for (int i = t; i < 1536; i += 256) {           // Y = A @ Xq   [96,16]
        int n = i >> 4, c = i & 15;
        float acc = 0.f;
        #pragma unroll 8
        for (int m = 0; m < 96; m++) acc += sA[n * 97 + m] * sX[m * 16 + c];
        sY[n * 16 + c] = acc;
    }
    __syncthreads();

    float* out = g_buf1 + (size_t)b * 6144;          // [n][f] 96*64
    for (int i = t; i < 6144; i += 256) {
        int n = i >> 6, f = i & 63;
        float acc = sB[f];
        #pragma unroll
        for (int c = 0; c < 16; c++) acc += sY[n * 16 + c] * sW[c * 64 + f];
        out[i] = fmaxf(acc, 0.f);
    }
}

// ---------------- GCN2: out = relu(A @ (Hq @ W2q) + b2), stored transposed ---
__global__ void k_gcn2(const float* __restrict__ W2, const float* __restrict__ b2) {
    extern __shared__ float sm[];
    float* sA = sm;               // 96*97, exact
    float* sH = sA + 9312;        // 96*64, tf32
    float* sT = sH + 6144;        // 96*32, exact intermediate
    float* sW = sT + 3072;        // 64*32, tf32
    float* sB = sW + 2048;        // 32
    int t = threadIdx.x, b = blockIdx.x;

    for (int i = t; i < 9216; i += 256) sA[(i / 96) * 97 + (i % 96)] = g_A[i];
    const float* hb = g_buf1 + (size_t)b * 6144;
    for (int i = t; i < 6144; i += 256) sH[i] = tf32r(hb[i]);
    for (int i = t; i < 2048; i += 256) sW[i] = tf32r(W2[i]);
    if (t < 32) sB[t] = b2[t];
    __syncthreads();

    for (int i = t; i < 3072; i += 256) {           // T = Hq @ W2q  [96,32]
        int n = i >> 5, g = i & 31;
        float acc = 0.f;
        #pragma unroll 8
        for (int f = 0; f < 64; f++) acc += sH[n * 64 + f] * sW[f * 32 + g];
        sT[n * 32 + g] = acc;
    }
    __syncthreads();

    float* out = g_buf2 + (size_t)b * 3072;          // write [g][n] (== conv input [C][L])
    for (int i = t; i < 3072; i += 256) {
        int g = i / 96, n = i % 96;
        float acc = sB[g];
        #pragma unroll 8
        for (int m = 0; m < 96; m++) acc += sA[n * 97 + m] * sT[m * 32 + g];
        out[i] = fmaxf(acc, 0.f);
    }
}

// ---------------- conv1: [B,32,96] -> [B,64,48], k=7 s=2 p=3, relu (TF32) ---
__global__ void __launch_bounds__(256, 2) k_conv1(const float* __restrict__ w,
                                                  const float* __restrict__ bias) {
    extern __shared__ float sm[];
    float* sIn = sm;                    // [4][32][104], padded, offset 3
    float* sW  = sIn + 4 * 32 * 104;    // [64][225] (padded row)
    int t = threadIdx.x;
    int b0 = blockIdx.x * 4;

    for (int i = t; i < 4 * 32 * 104; i += 256) {
        int lb = i / (32 * 104); int r = i % (32 * 104); int c = r / 104; int j = r % 104;
        int p = j - 3;
        float v = 0.f;
        if (p >= 0 && p < 96) v = tf32r(g_buf2[(size_t)(b0 + lb) * 3072 + c * 96 + p]);
        sIn[i] = v;
    }
    for (int i = t; i < 64 * 224; i += 256) sW[(i / 224) * 225 + (i % 224)] = tf32r(w[i]);
    __syncthreads();

    int lb = t >> 6, o = t & 63;
    const float* in = sIn + lb * 32 * 104;
    const float* wrow = sW + o * 225;
    float acc[48];
    float bo = bias[o];
    #pragma unroll
    for (int i = 0; i < 48; i++) acc[i] = bo;

    for (int c = 0; c < 32; c++) {
        float wr[7];
        #pragma unroll
        for (int k = 0; k < 7; k++) wr[k] = wrow[c * 7 + k];
        const float* ir = in + c * 104;
        #pragma unroll
        for (int tg = 0; tg < 4; tg++) {
            float win[29];
            #pragma unroll
            for (int j = 0; j < 29; j++) win[j] = ir[tg * 24 + j];
            #pragma unroll
            for (int tt = 0; tt < 12; tt++) {
                #pragma unroll
                for (int k = 0; k < 7; k++)
                    acc[tg * 12 + tt] += wr[k] * win[2 * tt + k];
            }
        }
    }
    float* out = g_buf1 + (size_t)(b0 + lb) * 3072 + o * 48;
    #pragma unroll
    for (int i = 0; i < 48; i++) out[i] = fmaxf(acc[i], 0.f);
}

// ---------------- conv2: [B,64,48] -> [B,128,24], k=5 s=2 p=2, relu (TF32) --
__global__ void __launch_bounds__(256, 1) k_conv2(const float* __restrict__ w,
                                                  const float* __restrict__ bias) {
    extern __shared__ float sm[];
    float* sIn = sm;                    // [2][64][52], offset 2
    float* sW  = sIn + 2 * 64 * 52;     // [128][321]
    int t = threadIdx.x;
    int b0 = blockIdx.x * 2;

    for (int i = t; i < 2 * 64 * 52; i += 256) {
        int lb = i / (64 * 52); int r = i % (64 * 52); int c = r / 52; int j = r % 52;
        int p = j - 2;
        float v = 0.f;
        if (p >= 0 && p < 48) v = tf32r(g_buf1[(size_t)(b0 + lb) * 3072 + c * 48 + p]);
        sIn[i] = v;
    }
    for (int i = t; i < 128 * 320; i += 256) sW[(i / 320) * 321 + (i % 320)] = tf32r(w[i]);
    __syncthreads();

    int lb = t >> 7, o = t & 127;
    const float* in = sIn + lb * 64 * 52;
    const float* wrow = sW + o * 321;
    float acc[24];
    float bo = bias[o];
    #pragma unroll
    for (int i = 0; i < 24; i++) acc[i] = bo;

    for (int c = 0; c < 64; c++) {
        float wr[5];
        #pragma unroll
        for (int k = 0; k < 5; k++) wr[k] = wrow[c * 5 + k];
        const float* ir = in + c * 52;
        #pragma unroll
        for (int tg = 0; tg < 2; tg++) {
            float win[27];
            #pragma unroll
            for (int j = 0; j < 27; j++) win[j] = ir[tg * 24 + j];
            #pragma unroll
            for (int tt = 0; tt < 12; tt++) {
                #pragma unroll
                for (int k = 0; k < 5; k++)
                    acc[tg * 12 + tt] += wr[k] * win[2 * tt + k];
            }
        }
    }
    float* out = g_buf2 + (size_t)(b0 + lb) * 3072 + o * 24;
    #pragma unroll
    for (int i = 0; i < 24; i++) out[i] = fmaxf(acc[i], 0.f);
}

// ---------------- conv3: [B,128,24] -> [B,256,12], k=3 s=2 p=1, relu (TF32) -
__global__ void __launch_bounds__(256, 1) k_conv3(const float* __restrict__ w,
                                                  const float* __restrict__ bias) {
    extern __shared__ float sm[];
    float* sIn = sm;                    // [2][128][26], offset 1
    float* sW  = sIn + 2 * 128 * 26;    // [128][385] per o-chunk
    int t = threadIdx.x;
    int b0 = blockIdx.x * 2;

    for (int i = t; i < 2 * 128 * 26; i += 256) {
        int lb = i / (128 * 26); int r = i % (128 * 26); int c = r / 26; int j = r % 26;
        int p = j - 1;
        float v = 0.f;
        if (p >= 0 && p < 24) v = tf32r(g_buf2[(size_t)(b0 + lb) * 3072 + c * 24 + p]);
        sIn[i] = v;
    }

    int lb = t >> 7, ol = t & 127;
    const float* in = sIn + lb * 128 * 26;

    for (int ch = 0; ch < 2; ch++) {
        __syncthreads();
        for (int i = t; i < 128 * 384; i += 256)
            sW[(i / 384) * 385 + (i % 384)] = tf32r(w[ch * 128 * 384 + i]);
        __syncthreads();

        int o = ch * 128 + ol;
        const float* wrow = sW + ol * 385;
        float acc[12];
        float bo = bias[o];
        #pragma unroll
        for (int i = 0; i < 12; i++) acc[i] = bo;

        for (int c = 0; c < 128; c++) {
            float wr[3];
            #pragma unroll
            for (int k = 0; k < 3; k++) wr[k] = wrow[c * 3 + k];
            const float* ir = in + c * 26;
            float win[25];
            #pragma unroll
            for (int j = 0; j < 25; j++) win[j] = ir[j];
            #pragma unroll
            for (int tt = 0; tt < 12; tt++) {
                #pragma unroll
                for (int k = 0; k < 3; k++)
                    acc[tt] += wr[k] * win[2 * tt + k];
            }
        }
        float* out = g_buf1 + (size_t)(b0 + lb) * 3072 + o * 12;
        #pragma unroll
        for (int i = 0; i < 12; i++) out[i] = fmaxf(acc[i], 0.f);
    }
}

// ---------------- fc1: [B,3072]@[3072,128]+b -> feat (out) & relu (scratch) --
__global__ void k_fc1(const float* __restrict__ W, const float* __restrict__ bias,
                      float* __restrict__ feat_out) {
    __shared__ __align__(16) float sA[32 * 33];
    __shared__ __align__(16) float sB[32 * 128];
    int t = threadIdx.x;
    int row0 = blockIdx.x * 32;
    int rg = t >> 5;     // row group (0..7) -> rows rg*4..rg*4+3
    int cg = t & 31;     // col group -> cols cg*4..cg*4+3
    float acc[4][4] = {};
    const float* Ain = g_buf1 + (size_t)row0 * 3072;

    for (int k0 = 0; k0 < 3072; k0 += 32) {
        for (int i = t; i < 32 * 32; i += 256) {
            int m = i >> 5, kk = i & 31;
            sA[m * 33 + kk] = tf32r(Ain[(size_t)m * 3072 + k0 + kk]);
        }
        for (int i = t; i < 32 * 128; i += 256) {
            int kk = i >> 7, n = i & 127;
            sB[i] = tf32r(W[(size_t)(k0 + kk) * 128 + n]);
        }
        __syncthreads();
        #pragma unroll
        for (int kk = 0; kk < 32; kk++) {
            float a[4];
            #pragma unroll
            for (int i = 0; i < 4; i++) a[i] = sA[(rg * 4 + i) * 33 + kk];
            float4 b4 = *(const float4*)&sB[kk * 128 + cg * 4];
            float bb[4] = {b4.x, b4.y, b4.z, b4.w};
            #pragma unroll
            for (int i = 0; i < 4; i++) {
                #pragma unroll
                for (int j = 0; j < 4; j++) acc[i][j] += a[i] * bb[j];
            }
        }
        __syncthreads();
    }
    #pragma unroll
    for (int i = 0; i < 4; i++) {
        int r = row0 + rg * 4 + i;
        #pragma unroll
        for (int j = 0; j < 4; j++) {
            int n = cg * 4 + j;
            float f = acc[i][j] + bias[n];
            feat_out[(size_t)r * 128 + n] = f;            // feat (pre-relu)
            g_buf2[(size_t)r * 128 + n] = fmaxf(f, 0.f);  // relu for cls stage
        }
    }
}

// ---------------- cls1: relu([B,128]@[128,128]+b) (TF32) --------------------
__global__ void k_cls1(const float* __restrict__ W, const float* __restrict__ bias) {
    extern __shared__ float sm[];
    float* sIn = sm;              // [64][129]
    float* sW  = sIn + 64 * 129;  // [128][128]
    int t = threadIdx.x;
    int b0 = blockIdx.x * 64;
    for (int i = t; i < 64 * 128; i += 256) {
        int r = i >> 7, k = i & 127;
        sIn[r * 129 + k] = tf32r(g_buf2[(size_t)(b0 + r) * 128 + k]);
    }
    for (int i = t; i < 128 * 128; i += 256) sW[i] = tf32r(W[i]);
    __syncthreads();
    for (int idx = t; idx < 64 * 128; idx += 256) {
        int r = idx >> 7, n = idx & 127;
        float acc = bias[n];
        #pragma unroll 8
        for (int k = 0; k < 128; k++) acc += sIn[r * 129 + k] * sW[k * 128 + n];
        g_buf1[(size_t)(b0 + r) * 128 + n] = fmaxf(acc, 0.f);
    }
}

// ---------------- cls2: [B,128]@[128,210]+b -> x (out) (TF32) ---------------
__global__ void k_cls2(const float* __restrict__ W, const float* __restrict__ bias,
                       float* __restrict__ out_x) {
    extern __shared__ float sm[];
    float* sIn = sm;              // [64][129]
    float* sW  = sIn + 64 * 129;  // [128][210]
    int t = threadIdx.x;
    int b0 = blockIdx.x * 64;
    for (int i = t; i < 64 * 128; i += 256) {
        int r = i >> 7, k = i & 127;
        sIn[r * 129 + k] = tf32r(g_buf1[(size_t)(b0 + r) * 128 + k]);
    }
    for (int i = t; i < 128 * 210; i += 256) sW[i] = tf32r(W[i]);
    __syncthreads();
    for (int idx = t; idx < 64 * 210; idx += 256) {
        int r = idx / 210, n = idx % 210;
        float acc = bias[n];
        #pragma unroll 8
        for (int k = 0; k < 128; k++) acc += sIn[r * 129 + k] * sW[k * 210 + n];
        out_x[(size_t)(b0 + r) * 210 + n] = acc;
    }
}

// ---------------- launch -----------------------------------------------------
extern "C" void kernel_launch(void* const* d_in, const int* in_sizes, int n_in,
                              void* d_out, int out_size) {
    const float* src     = (const float*)d_in[0];
    const int*   ei      = (const int*)d_in[1];
    const float* gcn1_w  = (const float*)d_in[2];
    const float* gcn1_b  = (const float*)d_in[3];
    const float* gcn2_w  = (const float*)d_in[4];
    const float* gcn2_b  = (const float*)d_in[5];
    const float* conv1_w = (const float*)d_in[6];
    const float* conv1_b = (const float*)d_in[7];
    const float* conv2_w = (const float*)d_in[8];
    const float* conv2_b = (const float*)d_in[9];
    const float* conv3_w = (const float*)d_in[10];
    const float* conv3_b = (const float*)d_in[11];
    const float* fc1_w   = (const float*)d_in[12];
    const float* fc1_b   = (const float*)d_in[13];
    const float* cls1_w  = (const float*)d_in[14];
    const float* cls1_b  = (const float*)d_in[15];
    const float* cls2_w  = (const float*)d_in[16];
    const float* cls2_b  = (const float*)d_in[17];

    int ne = in_sizes[1] / 2;                    // number of edges (E)

    float* out   = (float*)d_out;
    float* out_x = out;                          // [B,210]
    float* out_f = out + (size_t)BB * 210;       // [B,128]

    cudaFuncSetAttribute(k_gcn1,  cudaFuncAttributeMaxDynamicSharedMemorySize, 53888);
    cudaFuncSetAttribute(k_gcn2,  cudaFuncAttributeMaxDynamicSharedMemorySize, 82432);
    cudaFuncSetAttribute(k_conv1, cudaFuncAttributeMaxDynamicSharedMemorySize, 110848);
    cudaFuncSetAttribute(k_conv2, cudaFuncAttributeMaxDynamicSharedMemorySize, 190976);
    cudaFuncSetAttribute(k_conv3, cudaFuncAttributeMaxDynamicSharedMemorySize, 223744);
    cudaFuncSetAttribute(k_cls1,  cudaFuncAttributeMaxDynamicSharedMemorySize, 98560);
    cudaFuncSetAttribute(k_cls2,  cudaFuncAttributeMaxDynamicSharedMemorySize, 140544);

    k_build_adj<<<1, 256>>>(ei, ne);
    k_gcn1<<<BB, 256, 53888>>>(src, gcn1_w, gcn1_b);
    k_gcn2<<<BB, 256, 82432>>>(gcn2_w, gcn2_b);
    k_conv1<<<BB / 4, 256, 110848>>>(conv1_w, conv1_b);
    k_conv2<<<BB / 2, 256, 190976>>>(conv2_w, conv2_b);
    k_conv3<<<BB / 2, 256, 223744>>>(conv3_w, conv3_b);
    k_fc1<<<BB / 32, 256>>>(fc1_w, fc1_b, out_f);
    k_cls1<<<BB / 64, 256, 98560>>>(cls1_w, cls1_b);
    k_cls2<<<BB / 64, 256, 140544>>>(cls2_w, cls2_b, out_x);
}

// round 5
// speedup vs baseline: 1.6097x; 1.6097x over previous
#include <cuda_runtime.h>
#include <cstdint>
#include <math.h>

#define BB 8192

// TF32 operand rounding (matches cuBLAS/cuDNN TF32)
__device__ __forceinline__ float tf32r(float x) {
    uint32_t u;
    asm("cvt.rna.tf32.f32 %0, %1;" : "=r"(u) : "f"(x));
    return __uint_as_float(u);
}

// ---------------- scratch ----------------------------------------------------
__device__ float g_A[96 * 96];                 // A[n][m]
__device__ float g_At[96 * 96];                // A^T: [m][n]
__device__ float g_buf1[(size_t)BB * 6144];
__device__ float g_buf2[(size_t)BB * 3072];

// ---------------- build dense normalized adjacency (+ transpose) -------------
__global__ void k_build_adj(const int* __restrict__ ei, int ne) {
    __shared__ float deg[96];
    __shared__ float dinv[96];
    int t = threadIdx.x;
    if (t < 96) deg[t] = 0.f;
    for (int i = t; i < 9216; i += 256) { g_A[i] = 0.f; g_At[i] = 0.f; }
    __syncthreads();
    for (int e = t; e < ne; e += 256) atomicAdd(&deg[ei[e]], 1.0f);
    if (t < 96) atomicAdd(&deg[t], 1.0f);
    __syncthreads();
    if (t < 96) dinv[t] = 1.0f / sqrtf(fmaxf(deg[t], 1e-12f));
    __syncthreads();
    for (int e = t; e < ne; e += 256) {
        int r = ei[e], c = ei[ne + e];
        float v = dinv[r] * dinv[c];
        atomicAdd(&g_A[r * 96 + c], v);
        atomicAdd(&g_At[c * 96 + r], v);
    }
    if (t < 96) {
        float v = dinv[t] * dinv[t];
        atomicAdd(&g_A[t * 96 + t], v);
        atomicAdd(&g_At[t * 96 + t], v);
    }
}

// ---------------- fused GCN1+GCN2 (one block = one batch) --------------------
// Y = A@Xq (exact); H = tf32(relu(Y@W1q + b1)); T = H@W2q (exact);
// out = relu(A@T + b2) stored transposed [g][n] -> conv input layout.
__global__ void __launch_bounds__(256, 2) k_gcn(const float* __restrict__ src,
                                                const float* __restrict__ W1,
                                                const float* __restrict__ b1,
                                                const float* __restrict__ W2,
                                                const float* __restrict__ b2) {
    extern __shared__ float sm[];
    float* sAt = sm;              // [m][n] 96*96
    float* sX  = sAt + 9216;     // [m][c] pad 20, 96*20
    float* sYt = sX + 1920;     // [c][n] 16*96
    float* sW1 = sYt + 1536;     // [c][f] 16*64
    float* sHt = sW1 + 1024;     // [f][n] 64*96
    float* sW2 = sHt + 6144;     // [f][g] 64*32
    float* sT  = sW2 + 2048;     // [m][g] 96*32
    float* sB1 = sT + 3072;      // 64
    float* sB2 = sB1 + 64;       // 32
    int t = threadIdx.x, b = blockIdx.x;

    for (int i = t; i < 9216; i += 256) sAt[i] = g_At[i];   // already transposed
    const float* xb = src + (size_t)b * 1536;               // [c][m]
    for (int i = t; i < 1536; i += 256) { int c = i / 96, m = i % 96; sX[m * 20 + c] = tf32r(xb[i]); }
    for (int i = t; i < 1024; i += 256) sW1[i] = tf32r(W1[i]);
    for (int i = t; i < 2048; i += 256) sW2[i] = tf32r(W2[i]);
    if (t < 64) sB1[t] = b1[t];
    if (t < 32) sB2[t] = b2[t];
    __syncthreads();

    // Stage 1: Y[n][c] = sum_m A[n][m] Xq[m][c]  -> sYt[c][n] (exact)
    if (t < 96) {
        int n0 = (t % 24) * 4, c0 = (t / 24) * 4;
        float acc[4][4] = {};
        for (int m = 0; m < 96; m++) {
            float4 a4 = *(const float4*)&sAt[m * 96 + n0];
            float4 x4 = *(const float4*)&sX[m * 20 + c0];
            float av[4] = {a4.x, a4.y, a4.z, a4.w};
            float xv[4] = {x4.x, x4.y, x4.z, x4.w};
            #pragma unroll
            for (int ci = 0; ci < 4; ci++)
                #pragma unroll
                for (int nj = 0; nj < 4; nj++) acc[ci][nj] += xv[ci] * av[nj];
        }
        #pragma unroll
        for (int ci = 0; ci < 4; ci++)
            #pragma unroll
            for (int nj = 0; nj < 4; nj++) sYt[(c0 + ci) * 96 + n0 + nj] = acc[ci][nj];
    }
    __syncthreads();

    // Stage 2: H[n][f] = Y@W1q + b1, relu, tf32 -> sHt[f][n]
    for (int tile = t; tile < 384; tile += 256) {
        int n0 = (tile % 24) * 4, f0 = (tile / 24) * 4;
        float acc[4][4] = {};
        #pragma unroll
        for (int c = 0; c < 16; c++) {
            float4 y4 = *(const float4*)&sYt[c * 96 + n0];
            float4 w4 = *(const float4*)&sW1[c * 64 + f0];
            float yv[4] = {y4.x, y4.y, y4.z, y4.w};
            float wv[4] = {w4.x, w4.y, w4.z, w4.w};
            #pragma unroll
            for (int nj = 0; nj < 4; nj++)
                #pragma unroll
                for (int fi = 0; fi < 4; fi++) acc[nj][fi] += yv[nj] * wv[fi];
        }
        #pragma unroll
        for (int fi = 0; fi < 4; fi++)
            #pragma unroll
            for (int nj = 0; nj < 4; nj++)
                sHt[(f0 + fi) * 96 + n0 + nj] = tf32r(fmaxf(acc[nj][fi] + sB1[f0 + fi], 0.f));
    }
    __syncthreads();

    // Stage 3: T[n][g] = Hq@W2q (exact) -> sT[n][g]
    if (t < 192) {
        int n0 = (t % 24) * 4, g0 = (t / 24) * 4;
        float acc[4][4] = {};
        for (int f = 0; f < 64; f++) {
            float4 h4 = *(const float4*)&sHt[f * 96 + n0];
            float4 w4 = *(const float4*)&sW2[f * 32 + g0];
            float hv[4] = {h4.x, h4.y, h4.z, h4.w};
            float wv[4] = {w4.x, w4.y, w4.z, w4.w};
            #pragma unroll
            for (int nj = 0; nj < 4; nj++)
                #pragma unroll
                for (int gi = 0; gi < 4; gi++) acc[nj][gi] += hv[nj] * wv[gi];
        }
        #pragma unroll
        for (int nj = 0; nj < 4; nj++)
            #pragma unroll
            for (int gi = 0; gi < 4; gi++) sT[(n0 + nj) * 32 + g0 + gi] = acc[nj][gi];
    }
    __syncthreads();

    // Stage 4: out[g][n] = relu(sum_m A[n][m] T[m][g] + b2)
    if (t < 192) {
        int n0 = (t % 24) * 4, g0 = (t / 24) * 4;
        float acc[4][4] = {};
        for (int m = 0; m < 96; m++) {
            float4 a4 = *(const float4*)&sAt[m * 96 + n0];
            float4 t4 = *(const float4*)&sT[m * 32 + g0];
            float av[4] = {a4.x, a4.y, a4.z, a4.w};
            float tv[4] = {t4.x, t4.y, t4.z, t4.w};
            #pragma unroll
            for (int nj = 0; nj < 4; nj++)
                #pragma unroll
                for (int gi = 0; gi < 4; gi++) acc[nj][gi] += av[nj] * tv[gi];
        }
        float* out = g_buf2 + (size_t)b * 3072;
        #pragma unroll
        for (int gi = 0; gi < 4; gi++)
            #pragma unroll
            for (int nj = 0; nj < 4; nj++)
                out[(g0 + gi) * 96 + n0 + nj] = fmaxf(acc[nj][gi] + sB2[g0 + gi], 0.f);
    }
}

// ---------------- conv1: [B,32,96]->[B,64,48], k=7 s=2 p=3 -------------------
// 4 batches/block, weight chunks of 8 channels, tg-pairs (acc[2][12])
__global__ void __launch_bounds__(256, 3) k_conv1(const float* __restrict__ w,
                                                  const float* __restrict__ bias) {
    extern __shared__ float sm[];
    float* sIn = sm;                    // [4][32][104] offset 3
    float* sW  = sIn + 4 * 32 * 104;    // [64][57] (8ch*7k + pad)
    int t = threadIdx.x;
    int b0 = blockIdx.x * 4;

    for (int i = t; i < 4 * 32 * 104; i += 256) {
        int lb = i / (32 * 104); int r = i % (32 * 104); int c = r / 104; int j = r % 104;
        int p = j - 3;
        float v = 0.f;
        if (p >= 0 && p < 96) v = tf32r(g_buf2[(size_t)(b0 + lb) * 3072 + c * 96 + p]);
        sIn[i] = v;
    }

    int lb = t >> 6, o = t & 63;
    const float* in = sIn + lb * 32 * 104;
    float bo = bias[o];

    for (int p = 0; p < 2; p++) {                 // tg pairs {0,1},{2,3}
        float acc[2][12];
        #pragma unroll
        for (int q = 0; q < 2; q++)
            #pragma unroll
            for (int i = 0; i < 12; i++) acc[q][i] = bo;

        for (int cc = 0; cc < 4; cc++) {          // channel chunks of 8
            __syncthreads();
            for (int i = t; i < 64 * 56; i += 256)
                sW[(i / 56) * 57 + (i % 56)] = tf32r(w[(i / 56) * 224 + cc * 56 + (i % 56)]);
            __syncthreads();
            const float* wrow = sW + o * 57;
            #pragma unroll
            for (int c = 0; c < 8; c++) {
                float wr[7];
                #pragma unroll
                for (int k = 0; k < 7; k++) wr[k] = wrow[c * 7 + k];
                const float* ir = in + (cc * 8 + c) * 104;
                #pragma unroll
                for (int q = 0; q < 2; q++) {
                    int tg = p * 2 + q;
                    float win[29];
                    #pragma unroll
                    for (int j = 0; j < 29; j++) win[j] = ir[tg * 24 + j];
                    #pragma unroll
                    for (int tt = 0; tt < 12; tt++)
                        #pragma unroll
                        for (int k = 0; k < 7; k++) acc[q][tt] += wr[k] * win[2 * tt + k];
                }
            }
        }
        float* out = g_buf1 + (size_t)(b0 + lb) * 3072 + o * 48;
        #pragma unroll
        for (int q = 0; q < 2; q++)
            #pragma unroll
            for (int i = 0; i < 12; i++) out[(p * 2 + q) * 12 + i] = fmaxf(acc[q][i], 0.f);
    }
}

// ---------------- conv2: [B,64,48]->[B,128,24], k=5 s=2 p=2 ------------------
// 2 batches/block, weight chunks of 16 channels, acc[24]
__global__ void __launch_bounds__(256, 3) k_conv2(const float* __restrict__ w,
                                                  const float* __restrict__ bias) {
    extern __shared__ float sm[];
    float* sIn = sm;                    // [2][64][52] offset 2
    float* sW  = sIn + 2 * 64 * 52;     // [128][81] (16ch*5k + pad)
    int t = threadIdx.x;
    int b0 = blockIdx.x * 2;

    for (int i = t; i < 2 * 64 * 52; i += 256) {
        int lb = i / (64 * 52); int r = i % (64 * 52); int c = r / 52; int j = r % 52;
        int p = j - 2;
        float v = 0.f;
        if (p >= 0 && p < 48) v = tf32r(g_buf1[(size_t)(b0 + lb) * 3072 + c * 48 + p]);
        sIn[i] = v;
    }

    int lb = t >> 7, o = t & 127;
    const float* in = sIn + lb * 64 * 52;
    float acc[24];
    float bo = bias[o];
    #pragma unroll
    for (int i = 0; i < 24; i++) acc[i] = bo;

    for (int cc = 0; cc < 4; cc++) {              // channel chunks of 16
        __syncthreads();
        for (int i = t; i < 128 * 80; i += 256)
            sW[(i / 80) * 81 + (i % 80)] = tf32r(w[(i / 80) * 320 + cc * 80 + (i % 80)]);
        __syncthreads();
        const float* wrow = sW + o * 81;
        #pragma unroll
        for (int c = 0; c < 16; c++) {
            float wr[5];
            #pragma unroll
            for (int k = 0; k < 5; k++) wr[k] = wrow[c * 5 + k];
            const float* ir = in + (cc * 16 + c) * 52;
            #pragma unroll
            for (int tg = 0; tg < 2; tg++) {
                float win[27];
                #pragma unroll
                for (int j = 0; j < 27; j++) win[j] = ir[tg * 24 + j];
                #pragma unroll
                for (int tt = 0; tt < 12; tt++)
                    #pragma unroll
                    for (int k = 0; k < 5; k++) acc[tg * 12 + tt] += wr[k] * win[2 * tt + k];
            }
        }
    }
    float* out = g_buf2 + (size_t)(b0 + lb) * 3072 + o * 24;
    #pragma unroll
    for (int i = 0; i < 24; i++) out[i] = fmaxf(acc[i], 0.f);
}

// ---------------- conv3: [B,128,24]->[B,256,12], k=3 s=2 p=1 -----------------
// 2 batches/block, 2 output channels per thread, weight chunks of 8 channels
__global__ void __launch_bounds__(256, 3) k_conv3(const float* __restrict__ w,
                                                  const float* __restrict__ bias) {
    extern __shared__ float sm[];
    float* sIn = sm;                    // [2][128][26] offset 1
    float* sW  = sIn + 2 * 128 * 26;    // [256][25] (8ch*3k + pad)
    int t = threadIdx.x;
    int b0 = blockIdx.x * 2;

    for (int i = t; i < 2 * 128 * 26; i += 256) {
        int lb = i / (128 * 26); int r = i % (128 * 26); int c = r / 26; int j = r % 26;
        int p = j - 1;
        float v = 0.f;
        if (p >= 0 && p < 24) v = tf32r(g_buf2[(size_t)(b0 + lb) * 3072 + c * 24 + p]);
        sIn[i] = v;
    }

    int lb = t >> 7, ol = t & 127;
    const float* in = sIn + lb * 128 * 26;
    float acc[2][12];
    #pragma unroll
    for (int q = 0; q < 2; q++) {
        float bo = bias[ol + q * 128];
        #pragma unroll
        for (int i = 0; i < 12; i++) acc[q][i] = bo;
    }

    for (int cc = 0; cc < 16; cc++) {             // channel chunks of 8
        __syncthreads();
        for (int i = t; i < 256 * 24; i += 256)
            sW[(i / 24) * 25 + (i % 24)] = tf32r(w[(i / 24) * 384 + cc * 24 + (i % 24)]);
        __syncthreads();
        #pragma unroll
        for (int c = 0; c < 8; c++) {
            float wr[2][3];
            #pragma unroll
            for (int q = 0; q < 2; q++)
                #pragma unroll
                for (int k = 0; k < 3; k++) wr[q][k] = sW[(ol + q * 128) * 25 + c * 3 + k];
            const float* ir = in + (cc * 8 + c) * 26;
            float win[25];
            #pragma unroll
            for (int j = 0; j < 25; j++) win[j] = ir[j];
            #pragma unroll
            for (int tt = 0; tt < 12; tt++)
                #pragma unroll
                for (int k = 0; k < 3; k++) {
                    acc[0][tt] += wr[0][k] * win[2 * tt + k];
                    acc[1][tt] += wr[1][k] * win[2 * tt + k];
                }
        }
    }
    #pragma unroll
    for (int q = 0; q < 2; q++) {
        float* out = g_buf1 + (size_t)(b0 + lb) * 3072 + (ol + q * 128) * 12;
        #pragma unroll
        for (int i = 0; i < 12; i++) out[i] = fmaxf(acc[q][i], 0.f);
    }
}

// ---------------- fc1: [B,3072]@[3072,128]+b -> feat & relu ------------------
// 32x128 block tile, 4x4 per thread, float4 smem loads
__global__ void __launch_bounds__(256) k_fc1(const float* __restrict__ W,
                                             const float* __restrict__ bias,
                                             float* __restrict__ feat_out) {
    __shared__ __align__(16) float sAt[32 * 36];   // [k][m], pad 36
    __shared__ __align__(16) float sB[32 * 128];   // [k][n]
    int t = threadIdx.x;
    int row0 = blockIdx.x * 32;
    int nt = t & 31, mt = t >> 5;                  // n0 = nt*4, m0 = mt*4
    float acc[4][4] = {};
    const float* Ain = g_buf1 + (size_t)row0 * 3072;

    for (int k0 = 0; k0 < 3072; k0 += 32) {
        __syncthreads();
        for (int i = t; i < 1024; i += 256) {
            int m = i >> 5, k = i & 31;
            sAt[k * 36 + m] = tf32r(Ain[(size_t)m * 3072 + k0 + k]);
        }
        for (int i = t; i < 4096; i += 256) {
            int k = i >> 7, n = i & 127;
            sB[i] = tf32r(W[(size_t)(k0 + k) * 128 + n]);
        }
        __syncthreads();
        #pragma unroll
        for (int k = 0; k < 32; k++) {
            float4 a4 = *(const float4*)&sAt[k * 36 + mt * 4];
            float4 b4 = *(const float4*)&sB[k * 128 + nt * 4];
            float av[4] = {a4.x, a4.y, a4.z, a4.w};
            float bv[4] = {b4.x, b4.y, b4.z, b4.w};
            #pragma unroll
            for (int i = 0; i < 4; i++)
                #pragma unroll
                for (int j = 0; j < 4; j++) acc[i][j] += av[i] * bv[j];
        }
    }
    #pragma unroll
    for (int i = 0; i < 4; i++) {
        int r = row0 + mt * 4 + i;
        #pragma unroll
        for (int j = 0; j < 4; j++) {
            int n = nt * 4 + j;
            float f = acc[i][j] + bias[n];
            feat_out[(size_t)r * 128 + n] = f;
            g_buf2[(size_t)r * 128 + n] = fmaxf(f, 0.f);
        }
    }
}

// ---------------- cls1: relu([B,128]@[128,128]+b) ----------------------------
__global__ void k_cls1(const float* __restrict__ W, const float* __restrict__ bias) {
    extern __shared__ float sm[];
    float* sIn = sm;              // [64][129]
    float* sW  = sIn + 64 * 129;  // [128][128]
    int t = threadIdx.x;
    int b0 = blockIdx.x * 64;
    for (int i = t; i < 64 * 128; i += 256) {
        int r = i >> 7, k = i & 127;
        sIn[r * 129 + k] = tf32r(g_buf2[(size_t)(b0 + r) * 128 + k]);
    }
    for (int i = t; i < 128 * 128; i += 256) sW[i] = tf32r(W[i]);
    __syncthreads();
    for (int idx = t; idx < 64 * 128; idx += 256) {
        int r = idx >> 7, n = idx & 127;
        float acc = bias[n];
        #pragma unroll 8
        for (int k = 0; k < 128; k++) acc += sIn[r * 129 + k] * sW[k * 128 + n];
        g_buf1[(size_t)(b0 + r) * 128 + n] = fmaxf(acc, 0.f);
    }
}

// ---------------- cls2: [B,128]@[128,210]+b -> x -----------------------------
__global__ void k_cls2(const float* __restrict__ W, const float* __restrict__ bias,
                       float* __restrict__ out_x) {
    extern __shared__ float sm[];
    float* sIn = sm;              // [64][129]
    float* sW  = sIn + 64 * 129;  // [128][210]
    int t = threadIdx.x;
    int b0 = blockIdx.x * 64;
    for (int i = t; i < 64 * 128; i += 256) {
        int r = i >> 7, k = i & 127;
        sIn[r * 129 + k] = tf32r(g_buf1[(size_t)(b0 + r) * 128 + k]);
    }
    for (int i = t; i < 128 * 210; i += 256) sW[i] = tf32r(W[i]);
    __syncthreads();
    for (int idx = t; idx < 64 * 210; idx += 256) {
        int r = idx / 210, n = idx % 210;
        float acc = bias[n];
        #pragma unroll 8
        for (int k = 0; k < 128; k++) acc += sIn[r * 129 + k] * sW[k * 210 + n];
        out_x[(size_t)(b0 + r) * 210 + n] = acc;
    }
}

// ---------------- launch ------------------------------------------------------
extern "C" void kernel_launch(void* const* d_in, const int* in_sizes, int n_in,
                              void* d_out, int out_size) {
    const float* src     = (const float*)d_in[0];
    const int*   ei      = (const int*)d_in[1];
    const float* gcn1_w  = (const float*)d_in[2];
    const float* gcn1_b  = (const float*)d_in[3];
    const float* gcn2_w  = (const float*)d_in[4];
    const float* gcn2_b  = (const float*)d_in[5];
    const float* conv1_w = (const float*)d_in[6];
    const float* conv1_b = (const float*)d_in[7];
    const float* conv2_w = (const float*)d_in[8];
    const float* conv2_b = (const float*)d_in[9];
    const float* conv3_w = (const float*)d_in[10];
    const float* conv3_b = (const float*)d_in[11];
    const float* fc1_w   = (const float*)d_in[12];
    const float* fc1_b   = (const float*)d_in[13];
    const float* cls1_w  = (const float*)d_in[14];
    const float* cls1_b  = (const float*)d_in[15];
    const float* cls2_w  = (const float*)d_in[16];
    const float* cls2_b  = (const float*)d_in[17];

    int ne = in_sizes[1] / 2;

    float* out   = (float*)d_out;
    float* out_x = out;                          // [B,210]
    float* out_f = out + (size_t)BB * 210;       // [B,128]

    const int GCN_SMEM   = (9216 + 1920 + 1536 + 1024 + 6144 + 2048 + 3072 + 96) * 4; // 100224
    const int CONV1_SMEM = (4 * 32 * 104 + 64 * 57) * 4;    // 67840
    const int CONV2_SMEM = (2 * 64 * 52 + 128 * 81) * 4;    // 68096
    const int CONV3_SMEM = (2 * 128 * 26 + 256 * 25) * 4;   // 52224

    cudaFuncSetAttribute(k_gcn,   cudaFuncAttributeMaxDynamicSharedMemorySize, GCN_SMEM);
    cudaFuncSetAttribute(k_conv1, cudaFuncAttributeMaxDynamicSharedMemorySize, CONV1_SMEM);
    cudaFuncSetAttribute(k_conv2, cudaFuncAttributeMaxDynamicSharedMemorySize, CONV2_SMEM);
    cudaFuncSetAttribute(k_conv3, cudaFuncAttributeMaxDynamicSharedMemorySize, CONV3_SMEM);
    cudaFuncSetAttribute(k_cls1,  cudaFuncAttributeMaxDynamicSharedMemorySize, 98560);
    cudaFuncSetAttribute(k_cls2,  cudaFuncAttributeMaxDynamicSharedMemorySize, 140544);

    k_build_adj<<<1, 256>>>(ei, ne);
    k_gcn<<<BB, 256, GCN_SMEM>>>(src, gcn1_w, gcn1_b, gcn2_w, gcn2_b);
    k_conv1<<<BB / 4, 256, CONV1_SMEM>>>(conv1_w, conv1_b);
    k_conv2<<<BB / 2, 256, CONV2_SMEM>>>(conv2_w, conv2_b);
    k_conv3<<<BB / 2, 256, CONV3_SMEM>>>(conv3_w, conv3_b);
    k_fc1<<<BB / 32, 256>>>(fc1_w, fc1_b, out_f);
    k_cls1<<<BB / 64, 256, 98560>>>(cls1_w, cls1_b);
    k_cls2<<<BB / 64, 256, 140544>>>(cls2_w, cls2_b, out_x);
}